// round 14
// baseline (speedup 1.0000x reference)
#include <cuda_runtime.h>
#include <cstdint>

typedef unsigned long long ull;

#define TT 512
#define BB_ 256
#define DIN 64
#define HH 256
#define GG 1024   // 4*H
#define DOUT 8

#define CL 8            // CTAs per cluster
#define NCLUST 16       // clusters
#define NBC 16          // batches per cluster
#define NGR 4           // pipeline groups
#define NBGR 4          // batches per group
#define NCTA (NCLUST*CL)
#define NTC 512         // compute threads
#define NT  576         // compute + 2 epilogue warps
#define BAR_CNT (NTC + 32)   // 544 participants per group barrier

// ---------------- device scratch (static, allowed) ----------------
__device__ __align__(128) float g_Xp[(size_t)BB_*TT*GG];   // [b][t][rr]
__device__ __align__(128) float g_Wt[(size_t)HH*GG];       // [k][rr] reordered W_hh
__device__ __align__(128) float g_Wr_ih[(size_t)GG*DIN];
__device__ __align__(128) float g_br[GG];

// ---------------- helpers ----------------
__device__ __forceinline__ ull dupf(float f){ unsigned u=__float_as_uint(f); return (ull)u | ((ull)u<<32); }
__device__ __forceinline__ float lof(ull v){ return __uint_as_float((unsigned)v); }
__device__ __forceinline__ float hif(ull v){ return __uint_as_float((unsigned)(v>>32)); }
#define FMA2(acc,a,b) asm("fma.rn.f32x2 %0, %1, %2, %0;" : "+l"(acc) : "l"(a), "l"(b))
#define ADD2(d,a,b)   asm("add.rn.f32x2 %0, %1, %2;" : "=l"(d) : "l"(a), "l"(b))
#define TANHA(d,x)    asm("tanh.approx.f32 %0, %1;" : "=f"(d) : "f"(x))

#define CLUSTER_SYNC() do { \
    asm volatile("barrier.cluster.arrive.aligned;" ::: "memory"); \
    asm volatile("barrier.cluster.wait.aligned;"   ::: "memory"); } while(0)

// producer/consumer named barriers (ids 1..4)
#define BAR_ARRIVE(id) asm volatile("bar.arrive %0, %1;" :: "r"(id), "r"(BAR_CNT) : "memory")
#define BAR_SYNCN(id)  asm volatile("bar.sync %0, %1;"   :: "r"(id), "r"(BAR_CNT) : "memory")

__device__ __forceinline__ void mbar_init(unsigned a, unsigned cnt){
    asm volatile("mbarrier.init.shared.b64 [%0], %1;" :: "r"(a), "r"(cnt) : "memory");
}
__device__ __forceinline__ void mbar_expect(unsigned a, unsigned tx){
    asm volatile("mbarrier.arrive.expect_tx.shared.b64 _, [%0], %1;" :: "r"(a), "r"(tx) : "memory");
}
__device__ __forceinline__ void mbar_wait_par(unsigned a, unsigned ph){
    asm volatile(
        "{\n\t.reg .pred P;\n"
        "W1_%=:\n\t"
        "mbarrier.try_wait.parity.acquire.cta.shared::cta.b64 P, [%0], %1, 0x989680;\n\t"
        "@P bra W2_%=;\n\t"
        "bra W1_%=;\n"
        "W2_%=:\n\t}"
        :: "r"(a), "r"(ph) : "memory");
}
__device__ __forceinline__ unsigned mapa_sh(unsigned addr, unsigned rank){
    unsigned r;
    asm("mapa.shared::cluster.u32 %0, %1, %2;" : "=r"(r) : "r"(addr), "r"(rank));
    return r;
}
__device__ __forceinline__ void st_async8(unsigned raddr, ull v, unsigned rmbar){
    asm volatile("st.async.weak.shared::cluster.mbarrier::complete_tx::bytes.b64 [%0], %1, [%2];"
                 :: "r"(raddr), "l"(v), "r"(rmbar) : "memory");
}

// ---------------- weight reorder (one-time) ----------------
// rr = 4*j + g  (g in order i,f,g,o), orig row = g*H + j
__global__ void reorder_whh_kernel(const float* __restrict__ W_hh) {
    int k = blockIdx.x;
    for (int rr = threadIdx.x; rr < GG; rr += blockDim.x) {
        int jj = rr >> 2, g = rr & 3;
        g_Wt[(size_t)k * GG + rr] = W_hh[(size_t)(g * HH + jj) * HH + k];
    }
}

__global__ void reorder_wih_kernel(const float* __restrict__ W_ih,
                                   const float* __restrict__ bias) {
    int rr = blockIdx.x;
    int jj = rr >> 2, g = rr & 3;
    int orig = g * HH + jj;
    if (threadIdx.x < DIN)
        g_Wr_ih[(size_t)rr * DIN + threadIdx.x] = W_ih[(size_t)orig * DIN + threadIdx.x];
    if (threadIdx.x == 0) g_br[rr] = bias[orig];
}

// ---------------- input projection GEMM (f32x2, 64m x 128n tile) ----------------
#define XP_SMEM (DIN*66*8 + DIN*132*4)   // As2 + Bs = 67584
__global__ void __launch_bounds__(256) xproj_kernel(const float* __restrict__ x) {
    extern __shared__ __align__(16) char xsm[];
    ull*   As2 = (ull*)xsm;                 // [k][66] dup'd x
    float* Bs  = (float*)(As2 + DIN * 66);  // [k][132]
    int m0 = blockIdx.x * 64, n0 = blockIdx.y * 128;
    int tid = threadIdx.x;

    for (int i = tid; i < 1024; i += 256) {
        int r  = i >> 4;       // m row 0..63
        int kq = i & 15;
        float4 v = ((const float4*)(x + (size_t)(m0 + r) * DIN))[kq];
        As2[(kq*4+0)*66 + r] = dupf(v.x); As2[(kq*4+1)*66 + r] = dupf(v.y);
        As2[(kq*4+2)*66 + r] = dupf(v.z); As2[(kq*4+3)*66 + r] = dupf(v.w);
    }
    for (int i = tid; i < 2048; i += 256) {
        int r  = i >> 4;       // n row 0..127
        int kq = i & 15;
        float4 w = ((const float4*)(g_Wr_ih + (size_t)(n0 + r) * DIN))[kq];
        Bs[(kq*4+0)*132 + r] = w.x; Bs[(kq*4+1)*132 + r] = w.y;
        Bs[(kq*4+2)*132 + r] = w.z; Bs[(kq*4+3)*132 + r] = w.w;
    }
    __syncthreads();

    int tm = (tid >> 4) << 2;     // 4 m rows
    int tn = (tid & 15) << 3;     // 8 n cols (4 f32x2 pairs)
    ull acc[4][4] = {};
    #pragma unroll 8
    for (int k = 0; k < DIN; k++) {
        ulonglong2 a01 = *(const ulonglong2*)&As2[k*66 + tm];
        ulonglong2 a23 = *(const ulonglong2*)&As2[k*66 + tm + 2];
        ulonglong2 b01 = *(const ulonglong2*)&Bs[k*132 + tn];
        ulonglong2 b23 = *(const ulonglong2*)&Bs[k*132 + tn + 4];
        ull am[4] = {a01.x, a01.y, a23.x, a23.y};
        #pragma unroll
        for (int i = 0; i < 4; i++) {
            FMA2(acc[i][0], am[i], b01.x); FMA2(acc[i][1], am[i], b01.y);
            FMA2(acc[i][2], am[i], b23.x); FMA2(acc[i][3], am[i], b23.y);
        }
    }
    ulonglong2 bias01 = *(const ulonglong2*)(g_br + n0 + tn);
    ulonglong2 bias23 = *(const ulonglong2*)(g_br + n0 + tn + 4);
    #pragma unroll
    for (int i = 0; i < 4; i++) {
        ulonglong2 r0, r1;
        ADD2(r0.x, acc[i][0], bias01.x); ADD2(r0.y, acc[i][1], bias01.y);
        ADD2(r1.x, acc[i][2], bias23.x); ADD2(r1.y, acc[i][3], bias23.y);
        float* orow = g_Xp + (size_t)(m0 + tm + i) * GG + n0 + tn;
        *(ulonglong2*)orow       = r0;
        *(ulonglong2*)(orow + 4) = r1;
    }
}

// ---------------- LSTM recurrence: warp-specialized epilogue ----------------
// smem: shG [4 g][2 par][4 b][256 k] ull 64KB | red [4 g][4b][16kq][64p] ull 128KB | mbar[8]
#define SHG_ULL    (NBGR*HH)                // 1024 per (group,parity)
#define REDB_ULL   (NBGR*16*64)             // 4096 per group buffer
#define RED_OFF_B  (NGR*2*SHG_ULL*8)        // 65536
#define MBAR_OFF   (RED_OFF_B + NGR*REDB_ULL*8)  // 65536+131072=196608
#define LSTM_SMEM  (MBAR_OFF + 128)

__global__ void __launch_bounds__(NT, 1) __cluster_dims__(CL, 1, 1)
lstm_kernel(const float* __restrict__ h0, const float* __restrict__ c0,
            float* __restrict__ out) {
    extern __shared__ __align__(16) char smem[];
    ull*   shg  = (ull*)smem;                        // [(g*2+par)*1024 + b*256 + k]
    ull*   redb = (ull*)(smem + RED_OFF_B);          // [g][b][kq][pair]
    const unsigned sh_u32 = (unsigned)__cvta_generic_to_shared(smem);

    const int tid   = threadIdx.x;
    const int wid   = tid >> 5;
    const int lane  = tid & 31;
    const int slice = blockIdx.x & (CL - 1);
    const int cl    = blockIdx.x >> 3;
    const int b0c   = cl * NBC;

    // ---- common prologue ----
    if (tid < 8) mbar_init(sh_u32 + MBAR_OFF + tid * 8, 1);

    // init parity-0 buffers from h0 (all threads)
    for (int i = tid; i < NBC * HH; i += NT) {
        int b = i >> 8, k = i & 255;
        shg[((b >> 2) * 2) * SHG_ULL + (b & 3) * HH + k] =
            dupf(h0[(size_t)(b0c + b) * HH + k]);
    }
    __syncthreads();
    CLUSTER_SYNC();            // mbarriers initialized cluster-wide before any st.async

    if (wid < 16) {
        // ================= COMPUTE WARPS =================
        const int kq    = tid >> 5;            // 0..15, 16 k each
        const int pg    = lane;                // j = slice*32 + pg
        const int kbase = kq * 16;

        ull wreg[32];
        #pragma unroll
        for (int kk = 0; kk < 16; kk++) {
            ulonglong2 w2 = *(const ulonglong2*)(g_Wt + (size_t)(kbase + kk) * GG
                                                 + slice * 128 + 4 * pg);
            wreg[2*kk]     = w2.x;
            wreg[2*kk + 1] = w2.y;
        }

        unsigned ph0[NGR] = {0,0,0,0};
        unsigned ph1[NGR] = {0,0,0,0};

        #pragma unroll 1
        for (int t = 0; t < TT; t++) {
            const int par = t & 1, nb = par ^ 1;
            const int last = (t == TT - 1);

            #pragma unroll
            for (int g = 0; g < NGR; g++) {
                const unsigned mb_par = sh_u32 + MBAR_OFF + (unsigned)((g * 2 + par) * 8);
                const unsigned mb_nb  = sh_u32 + MBAR_OFF + (unsigned)((g * 2 + nb) * 8);

                if (t) {
                    if (par) { mbar_wait_par(mb_par, ph1[g]); ph1[g] ^= 1; }
                    else     { mbar_wait_par(mb_par, ph0[g]); ph0[g] ^= 1; }
                }

                const ull* gb = shg + (size_t)(g * 2 + par) * SHG_ULL;
                ull* rb = redb + (size_t)g * REDB_ULL;
                #pragma unroll
                for (int b = 0; b < NBGR; b++) {
                    const ulonglong2* hp = (const ulonglong2*)(gb + b * HH + kbase);
                    ull a0 = 0ull, a1 = 0ull, a2 = 0ull, a3 = 0ull;
                    #pragma unroll
                    for (int kk = 0; kk < 16; kk += 2) {
                        ulonglong2 h2 = hp[kk >> 1];
                        FMA2(a0, wreg[2*kk],     h2.x);
                        FMA2(a1, wreg[2*kk + 1], h2.x);
                        FMA2(a2, wreg[2*kk + 2], h2.y);
                        FMA2(a3, wreg[2*kk + 3], h2.y);
                    }
                    ulonglong2 s;
                    ADD2(s.x, a0, a2);
                    ADD2(s.y, a1, a3);
                    *(ulonglong2*)(rb + (b * 16 + kq) * 64 + 2 * pg) = s;
                }

                if (tid == 0 && !last) mbar_expect(mb_nb, 8192);
                BAR_ARRIVE(g + 1);     // non-blocking; flow into next group
            }
        }
    } else {
        // ================= EPILOGUE WARPS =================
        const int ew = wid - 16;               // 0: groups 0,1   1: groups 2,3
        // lane owns j = slice*32 + lane for batches of its two groups
        float creg[2][NBGR], hlast[2][NBGR];
        #pragma unroll
        for (int gi = 0; gi < 2; gi++)
            #pragma unroll
            for (int q = 0; q < NBGR; q++)
                creg[gi][q] = c0[(size_t)(b0c + (2*ew + gi) * 4 + q) * HH
                                 + slice * 32 + lane];

        unsigned pbase[CL];
        #pragma unroll
        for (int r = 0; r < CL; r++) pbase[r] = mapa_sh(sh_u32, r);

        #pragma unroll 1
        for (int t = 0; t < TT; t++) {
            const int par = t & 1, nb = par ^ 1;
            const int last = (t == TT - 1);

            #pragma unroll
            for (int gi = 0; gi < 2; gi++) {
                const int g = 2 * ew + gi;
                // issue x loads early (L2-resident; latency hidden by bar wait)
                float4 xv[NBGR];
                #pragma unroll
                for (int q = 0; q < NBGR; q++)
                    xv[q] = *(const float4*)(g_Xp
                              + ((size_t)(b0c + g * 4 + q) * TT + t) * GG
                              + slice * 128 + 4 * lane);

                BAR_SYNCN(g + 1);      // all compute warps' red[g] writes done

                #pragma unroll
                for (int q = 0; q < NBGR; q++) {
                    const ull* rp = redb + (size_t)g * REDB_ULL + (q * 16) * 64 + 2 * lane;
                    ull sx[8], sy[8];
                    #pragma unroll
                    for (int u = 0; u < 8; u++) {
                        ulonglong2 a = *(const ulonglong2*)(rp + (2*u) * 64);
                        ulonglong2 b = *(const ulonglong2*)(rp + (2*u + 1) * 64);
                        ADD2(sx[u], a.x, b.x);
                        ADD2(sy[u], a.y, b.y);
                    }
                    ull sif, sgo, t0, t1, t2, t3;
                    ADD2(t0, sx[0], sx[1]); ADD2(t1, sx[2], sx[3]);
                    ADD2(t2, sx[4], sx[5]); ADD2(t3, sx[6], sx[7]);
                    ADD2(t0, t0, t1); ADD2(t2, t2, t3); ADD2(sif, t0, t2);
                    ADD2(t0, sy[0], sy[1]); ADD2(t1, sy[2], sy[3]);
                    ADD2(t2, sy[4], sy[5]); ADD2(t3, sy[6], sy[7]);
                    ADD2(t0, t0, t1); ADD2(t2, t2, t3); ADD2(sgo, t0, t2);

                    float pi  = xv[q].x + lof(sif);
                    float pf  = xv[q].y + hif(sif);
                    float pgx = xv[q].z + lof(sgo);
                    float po  = xv[q].w + hif(sgo);
                    float ti, tf_, tg, to, tc;
                    TANHA(ti, pi * 0.5f); TANHA(tf_, pf * 0.5f);
                    TANHA(tg, pgx);       TANHA(to, po * 0.5f);
                    float ig = fmaf(ti, 0.5f, 0.5f);
                    float fg = fmaf(tf_, 0.5f, 0.5f);
                    float og = fmaf(to, 0.5f, 0.5f);
                    creg[gi][q] = fg * creg[gi][q] + ig * tg;
                    TANHA(tc, creg[gi][q]);
                    hlast[gi][q] = og * tc;

                    if (!last) {
                        unsigned doff = (unsigned)((g * 2 + nb) * SHG_ULL * 8)
                                        + (unsigned)((q * HH + slice * 32 + lane) * 8);
                        unsigned moff = (unsigned)(MBAR_OFF + (g * 2 + nb) * 8);
                        ull hv = dupf(hlast[gi][q]);
                        #pragma unroll
                        for (int r = 0; r < CL; r++)
                            st_async8(pbase[r] + doff, hv, pbase[r] + moff);
                    }
                }
            }
        }

        // ---- outputs: rnn_outputs @0, logits @65536, h @67584, c @133120 ----
        #pragma unroll
        for (int gi = 0; gi < 2; gi++)
            #pragma unroll
            for (int q = 0; q < NBGR; q++) {
                size_t idx = (size_t)(b0c + (2*ew + gi) * 4 + q) * HH + slice * 32 + lane;
                out[idx]          = hlast[gi][q];
                out[67584 + idx]  = hlast[gi][q];
                out[133120 + idx] = creg[gi][q];
            }
    }

    CLUSTER_SYNC();            // no CTA exits while peers may still target our smem
}

// ---------------- output projection ----------------
__global__ void logits_kernel(const float* __restrict__ hbase,
                              const float* __restrict__ W_out,
                              const float* __restrict__ b_out,
                              float* __restrict__ out_logits) {
    int b = blockIdx.x;
    int d = threadIdx.x >> 5;
    int lane = threadIdx.x & 31;
    const float* hr = hbase + (size_t)b * HH;
    const float* wr = W_out + (size_t)d * HH;
    float s = 0.f;
    #pragma unroll
    for (int k = lane; k < HH; k += 32) s += hr[k] * wr[k];
    #pragma unroll
    for (int o = 16; o; o >>= 1) s += __shfl_down_sync(0xffffffffu, s, o);
    if (lane == 0) out_logits[b * DOUT + d] = s + b_out[d];
}

// ---------------- launch ----------------
extern "C" void kernel_launch(void* const* d_in, const int* in_sizes, int n_in,
                              void* d_out, int out_size) {
    const float* x     = (const float*)d_in[0];
    const float* h0    = (const float*)d_in[1];
    const float* c0    = (const float*)d_in[2];
    const float* W_ih  = (const float*)d_in[3];
    const float* W_hh  = (const float*)d_in[4];
    const float* bias  = (const float*)d_in[5];
    const float* W_out = (const float*)d_in[6];
    const float* b_out = (const float*)d_in[7];
    float* out = (float*)d_out;

    static int cfg_done = 0;
    if (!cfg_done) {
        cudaFuncSetAttribute(lstm_kernel, cudaFuncAttributeMaxDynamicSharedMemorySize,
                             LSTM_SMEM);
        cudaFuncSetAttribute(xproj_kernel, cudaFuncAttributeMaxDynamicSharedMemorySize,
                             XP_SMEM);
        cfg_done = 1;
    }

    reorder_whh_kernel<<<HH, 256>>>(W_hh);
    reorder_wih_kernel<<<GG, 64>>>(W_ih, bias);

    xproj_kernel<<<dim3((BB_ * TT) / 64, GG / 128), 256, XP_SMEM>>>(x);

    lstm_kernel<<<NCTA, NT, LSTM_SMEM>>>(h0, c0, out);

    logits_kernel<<<BB_, 256>>>(out, W_out, b_out, out + 65536);
}

// round 15
// speedup vs baseline: 1.0017x; 1.0017x over previous
#include <cuda_runtime.h>
#include <cstdint>

typedef unsigned long long ull;

#define TT 512
#define BB_ 256
#define DIN 64
#define HH 256
#define GG 1024   // 4*H
#define DOUT 8

#define CL 8            // CTAs per cluster
#define NCLUST 16       // clusters
#define NBC 16          // batches per cluster
#define NGR 4           // pipeline groups
#define NBGR 4          // batches per group
#define NCTA (NCLUST*CL)
#define NT 512          // threads per lstm CTA

// ---------------- device scratch (static, allowed) ----------------
__device__ __align__(128) float g_Xp[(size_t)BB_*TT*GG];   // [b][t][rr]
__device__ __align__(128) float g_Wt[(size_t)HH*GG];       // [k][rr] reordered W_hh
__device__ __align__(128) float g_Wr_ih[(size_t)GG*DIN];
__device__ __align__(128) float g_br[GG];

// ---------------- helpers ----------------
__device__ __forceinline__ ull dupf(float f){ unsigned u=__float_as_uint(f); return (ull)u | ((ull)u<<32); }
__device__ __forceinline__ float lof(ull v){ return __uint_as_float((unsigned)v); }
__device__ __forceinline__ float hif(ull v){ return __uint_as_float((unsigned)(v>>32)); }
#define FMA2(acc,a,b) asm("fma.rn.f32x2 %0, %1, %2, %0;" : "+l"(acc) : "l"(a), "l"(b))
#define ADD2(d,a,b)   asm("add.rn.f32x2 %0, %1, %2;" : "=l"(d) : "l"(a), "l"(b))
#define TANHA(d,x)    asm("tanh.approx.f32 %0, %1;" : "=f"(d) : "f"(x))

#define CP16(dst_s, src_g) \
    asm volatile("cp.async.cg.shared.global [%0], [%1], 16;" :: "r"(dst_s), "l"(src_g) : "memory")
#define CP_COMMIT()  asm volatile("cp.async.commit_group;" ::: "memory")
#define CP_WAIT(n)   asm volatile("cp.async.wait_group %0;" :: "n"(n) : "memory")
#define CLUSTER_SYNC() do { \
    asm volatile("barrier.cluster.arrive.aligned;" ::: "memory"); \
    asm volatile("barrier.cluster.wait.aligned;"   ::: "memory"); } while(0)

// producer/consumer named barriers (ids 1..4), all 512 threads participate
#define BAR_ARRIVE(id) asm volatile("bar.arrive %0, %1;" :: "r"(id), "r"(NT) : "memory")
#define BAR_SYNCN(id)  asm volatile("bar.sync %0, %1;"   :: "r"(id), "r"(NT) : "memory")

__device__ __forceinline__ void mbar_init(unsigned a, unsigned cnt){
    asm volatile("mbarrier.init.shared.b64 [%0], %1;" :: "r"(a), "r"(cnt) : "memory");
}
__device__ __forceinline__ void mbar_expect(unsigned a, unsigned tx){
    asm volatile("mbarrier.arrive.expect_tx.shared.b64 _, [%0], %1;" :: "r"(a), "r"(tx) : "memory");
}
__device__ __forceinline__ void mbar_wait_par(unsigned a, unsigned ph){
    asm volatile(
        "{\n\t.reg .pred P;\n"
        "W1_%=:\n\t"
        "mbarrier.try_wait.parity.acquire.cta.shared::cta.b64 P, [%0], %1, 0x989680;\n\t"
        "@P bra W2_%=;\n\t"
        "bra W1_%=;\n"
        "W2_%=:\n\t}"
        :: "r"(a), "r"(ph) : "memory");
}
__device__ __forceinline__ unsigned mapa_sh(unsigned addr, unsigned rank){
    unsigned r;
    asm("mapa.shared::cluster.u32 %0, %1, %2;" : "=r"(r) : "r"(addr), "r"(rank));
    return r;
}
__device__ __forceinline__ void st_async8(unsigned raddr, ull v, unsigned rmbar){
    asm volatile("st.async.weak.shared::cluster.mbarrier::complete_tx::bytes.b64 [%0], %1, [%2];"
                 :: "r"(raddr), "l"(v), "r"(rmbar) : "memory");
}

// ---------------- weight reorder (one-time) ----------------
// rr = 4*j + g  (g in order i,f,g,o), orig row = g*H + j
__global__ void reorder_whh_kernel(const float* __restrict__ W_hh) {
    int k = blockIdx.x;
    for (int rr = threadIdx.x; rr < GG; rr += blockDim.x) {
        int jj = rr >> 2, g = rr & 3;
        g_Wt[(size_t)k * GG + rr] = W_hh[(size_t)(g * HH + jj) * HH + k];
    }
}

__global__ void reorder_wih_kernel(const float* __restrict__ W_ih,
                                   const float* __restrict__ bias) {
    int rr = blockIdx.x;
    int jj = rr >> 2, g = rr & 3;
    int orig = g * HH + jj;
    if (threadIdx.x < DIN)
        g_Wr_ih[(size_t)rr * DIN + threadIdx.x] = W_ih[(size_t)orig * DIN + threadIdx.x];
    if (threadIdx.x == 0) g_br[rr] = bias[orig];
}

// ---------------- input projection GEMM (f32x2, 64m x 128n tile) ----------------
#define XP_SMEM (DIN*66*8 + DIN*132*4)   // As2 + Bs = 67584
__global__ void __launch_bounds__(256) xproj_kernel(const float* __restrict__ x) {
    extern __shared__ __align__(16) char xsm[];
    ull*   As2 = (ull*)xsm;                 // [k][66] dup'd x
    float* Bs  = (float*)(As2 + DIN * 66);  // [k][132]
    int m0 = blockIdx.x * 64, n0 = blockIdx.y * 128;
    int tid = threadIdx.x;

    for (int i = tid; i < 1024; i += 256) {
        int r  = i >> 4;       // m row 0..63
        int kq = i & 15;
        float4 v = ((const float4*)(x + (size_t)(m0 + r) * DIN))[kq];
        As2[(kq*4+0)*66 + r] = dupf(v.x); As2[(kq*4+1)*66 + r] = dupf(v.y);
        As2[(kq*4+2)*66 + r] = dupf(v.z); As2[(kq*4+3)*66 + r] = dupf(v.w);
    }
    for (int i = tid; i < 2048; i += 256) {
        int r  = i >> 4;       // n row 0..127
        int kq = i & 15;
        float4 w = ((const float4*)(g_Wr_ih + (size_t)(n0 + r) * DIN))[kq];
        Bs[(kq*4+0)*132 + r] = w.x; Bs[(kq*4+1)*132 + r] = w.y;
        Bs[(kq*4+2)*132 + r] = w.z; Bs[(kq*4+3)*132 + r] = w.w;
    }
    __syncthreads();

    int tm = (tid >> 4) << 2;     // 4 m rows
    int tn = (tid & 15) << 3;     // 8 n cols (4 f32x2 pairs)
    ull acc[4][4] = {};
    #pragma unroll 8
    for (int k = 0; k < DIN; k++) {
        ulonglong2 a01 = *(const ulonglong2*)&As2[k*66 + tm];
        ulonglong2 a23 = *(const ulonglong2*)&As2[k*66 + tm + 2];
        ulonglong2 b01 = *(const ulonglong2*)&Bs[k*132 + tn];
        ulonglong2 b23 = *(const ulonglong2*)&Bs[k*132 + tn + 4];
        ull am[4] = {a01.x, a01.y, a23.x, a23.y};
        #pragma unroll
        for (int i = 0; i < 4; i++) {
            FMA2(acc[i][0], am[i], b01.x); FMA2(acc[i][1], am[i], b01.y);
            FMA2(acc[i][2], am[i], b23.x); FMA2(acc[i][3], am[i], b23.y);
        }
    }
    ulonglong2 bias01 = *(const ulonglong2*)(g_br + n0 + tn);
    ulonglong2 bias23 = *(const ulonglong2*)(g_br + n0 + tn + 4);
    #pragma unroll
    for (int i = 0; i < 4; i++) {
        ulonglong2 r0, r1;
        ADD2(r0.x, acc[i][0], bias01.x); ADD2(r0.y, acc[i][1], bias01.y);
        ADD2(r1.x, acc[i][2], bias23.x); ADD2(r1.y, acc[i][3], bias23.y);
        float* orow = g_Xp + (size_t)(m0 + tm + i) * GG + n0 + tn;
        *(ulonglong2*)orow       = r0;
        *(ulonglong2*)(orow + 4) = r1;
    }
}

// ---------------- LSTM recurrence: 4-stage pipeline, per-source mbars ----------------
// smem: shG [4 g][2 par][4 b][256 k] ull 64KB | red [4 g][4b][16kq][64p] ull 128KB |
//       xbuf [2][16b][128] f 16KB | mbar[2 par][4 g][8 src]
#define SHG_ULL    (NBGR*HH)                // 1024 per (group,parity)
#define REDB_ULL   (NBGR*16*64)             // 4096 per group buffer
#define XBUF_F     (2*NBC*128)              // 4096
#define RED_OFF_B  (NGR*2*SHG_ULL*8)        // 65536
#define XBUF_OFF   (RED_OFF_B + NGR*REDB_ULL*8)  // 65536+131072=196608
#define MBAR_OFF   (XBUF_OFF + XBUF_F*4)         // 212992
#define NMBAR      (2*NGR*CL)                    // 64
#define LSTM_SMEM  (MBAR_OFF + NMBAR*8 + 64)

// mbar address: [par][g][src]
#define MB(par,g,src) (sh_u32 + MBAR_OFF + (unsigned)((((par)*NGR + (g))*CL + (src)) * 8))

__global__ void __launch_bounds__(NT, 1) __cluster_dims__(CL, 1, 1)
lstm_kernel(const float* __restrict__ h0, const float* __restrict__ c0,
            float* __restrict__ out) {
    extern __shared__ __align__(16) char smem[];
    ull*   shg  = (ull*)smem;                        // [(g*2+par)*1024 + b*256 + k]
    ull*   redb = (ull*)(smem + RED_OFF_B);          // [g][b][kq][pair]
    float* xbuf = (float*)(smem + XBUF_OFF);         // [buf][b][128]
    const unsigned sh_u32 = (unsigned)__cvta_generic_to_shared(smem);

    const int tid   = threadIdx.x;
    const int slice = blockIdx.x & (CL - 1);
    const int cl    = blockIdx.x >> 3;
    const int b0c   = cl * NBC;

    // mainloop mapping: kq warp-uniform (broadcast LDS), 2 gate-pairs/thread
    const int kq    = tid >> 5;                // 0..15, 16 k each
    const int pg    = tid & 31;                // pairs 2pg, 2pg+1
    const int kbase = kq * 16;
    const int mysrc = kq >> 1;                 // source slice of this warp's k segment

    // epilogue mapping
    const int jl  = tid & 31;                  // local j 0..31
    const int eb  = tid >> 5;                  // batch 0..15
    const int grp = eb >> 2;                   // pipeline group 0..3
    const int ebg = eb & 3;                    // batch within group

    // ---- prologue ----
    if (tid < NMBAR) mbar_init(sh_u32 + MBAR_OFF + tid * 8, 1);

    // resident weights: wreg[2*kk+p] = W[kbase+kk][slice*128 + 4*pg + 2p ..]
    ull wreg[32];
    #pragma unroll
    for (int kk = 0; kk < 16; kk++) {
        ulonglong2 w2 = *(const ulonglong2*)(g_Wt + (size_t)(kbase + kk) * GG
                                             + slice * 128 + 4 * pg);
        wreg[2*kk]     = w2.x;
        wreg[2*kk + 1] = w2.y;
    }

    // peer smem window bases (mapa hoisted out of the loop)
    unsigned pbase[CL];
    #pragma unroll
    for (int r = 0; r < CL; r++) pbase[r] = mapa_sh(sh_u32, r);

    // init parity-0 buffers from h0
    for (int i = tid; i < NBC * HH; i += NT) {
        int b = i >> 8, k = i & 255;
        shg[((b >> 2) * 2) * SHG_ULL + (b & 3) * HH + k] =
            dupf(h0[(size_t)(b0c + b) * HH + k]);
    }
    float creg = c0[(size_t)(b0c + eb) * HH + slice * 32 + jl];
    float hlast = 0.f;

    // this thread's h byte-offset within its group buffer
    const unsigned hoff = (unsigned)((ebg * HH + slice * 32 + jl) * 8);

    // prefetch x(0)
    {
        int b = tid >> 5, q = tid & 31;
        unsigned dst = (unsigned)__cvta_generic_to_shared(xbuf + b * 128 + q * 4);
        const float* src = g_Xp + ((size_t)(b0c + b) * TT + 0) * GG + slice * 128 + q * 4;
        CP16(dst, src);
        CP_COMMIT();
    }
    __syncthreads();
    CLUSTER_SYNC();            // mbarriers initialized cluster-wide before any st.async

    unsigned ph0[NGR] = {0,0,0,0};   // phase for parity-0 mbars (this warp's source)
    unsigned ph1[NGR] = {0,0,0,0};   // phase for parity-1 mbars

    // ---- time loop (no __syncthreads inside) ----
    #pragma unroll 1
    for (int t = 0; t < TT; t++) {
        const int par = t & 1, nb = par ^ 1;
        const int last = (t == TT - 1);

        #pragma unroll
        for (int g = 0; g < NGR; g++) {
            if (t) {
                // wait only this warp's source slice
                if (par) { mbar_wait_par(MB(1, g, mysrc), ph1[g]); ph1[g] ^= 1; }
                else     { mbar_wait_par(MB(0, g, mysrc), ph0[g]); ph0[g] ^= 1; }
            }

            // mainloop group g: 4 b, per b: 8 broadcast LDS.128, 32 FMA2
            {
                const ull* gb = shg + (size_t)(g * 2 + par) * SHG_ULL;
                ull* rb = redb + (size_t)g * REDB_ULL;
                #pragma unroll
                for (int b = 0; b < NBGR; b++) {
                    const ulonglong2* hp = (const ulonglong2*)(gb + b * HH + kbase);
                    ull a0 = 0ull, a1 = 0ull, a2 = 0ull, a3 = 0ull;
                    #pragma unroll
                    for (int kk = 0; kk < 16; kk += 2) {
                        ulonglong2 h2 = hp[kk >> 1];
                        FMA2(a0, wreg[2*kk],     h2.x);
                        FMA2(a1, wreg[2*kk + 1], h2.x);
                        FMA2(a2, wreg[2*kk + 2], h2.y);
                        FMA2(a3, wreg[2*kk + 3], h2.y);
                    }
                    ulonglong2 s;
                    ADD2(s.x, a0, a2);
                    ADD2(s.y, a1, a3);
                    *(ulonglong2*)(rb + (b * 16 + kq) * 64 + 2 * pg) = s;
                }
            }

            if (g == 0 && !last) {
                // x prefetch for t+1 (per-thread self-contained)
                int b = tid >> 5, q = tid & 31;
                unsigned dst = (unsigned)__cvta_generic_to_shared(
                    xbuf + ((size_t)nb * NBC + b) * 128 + q * 4);
                const float* src = g_Xp + ((size_t)(b0c + b) * TT + (t + 1)) * GG
                                   + slice * 128 + q * 4;
                CP16(dst, src);
                CP_COMMIT();
            }
            // distribute expects: one per source mbar of next parity
            if (tid < CL && !last) mbar_expect(MB(nb, g, tid), 1024);

            if (grp == g) {
                BAR_SYNCN(g + 1);      // consumers: wait all warps' red[g] writes
                // epilogue: thread owns (j = slice*32+jl, batch eb)
                const ull* rp = redb + (size_t)g * REDB_ULL + (ebg * 16) * 64 + 2 * jl;
                ull sx[8], sy[8];
                #pragma unroll
                for (int q = 0; q < 8; q++) {
                    ulonglong2 u = *(const ulonglong2*)(rp + (2*q) * 64);
                    ulonglong2 v = *(const ulonglong2*)(rp + (2*q + 1) * 64);
                    ADD2(sx[q], u.x, v.x);
                    ADD2(sy[q], u.y, v.y);
                }
                ull sif, sgo, t0, t1, t2, t3;
                ADD2(t0, sx[0], sx[1]); ADD2(t1, sx[2], sx[3]);
                ADD2(t2, sx[4], sx[5]); ADD2(t3, sx[6], sx[7]);
                ADD2(t0, t0, t1); ADD2(t2, t2, t3); ADD2(sif, t0, t2);
                ADD2(t0, sy[0], sy[1]); ADD2(t1, sy[2], sy[3]);
                ADD2(t2, sy[4], sy[5]); ADD2(t3, sy[6], sy[7]);
                ADD2(t0, t0, t1); ADD2(t2, t2, t3); ADD2(sgo, t0, t2);

                if (last) { CP_WAIT(0); } else { CP_WAIT(1); }
                float4 xv = *(const float4*)(xbuf + ((size_t)par * NBC + eb) * 128 + 4 * jl);
                float pi  = xv.x + lof(sif);
                float pf  = xv.y + hif(sif);
                float pgx = xv.z + lof(sgo);
                float po  = xv.w + hif(sgo);
                float ti, tf_, tg, to, tc;
                TANHA(ti, pi * 0.5f); TANHA(tf_, pf * 0.5f);
                TANHA(tg, pgx);       TANHA(to, po * 0.5f);
                float ig = fmaf(ti, 0.5f, 0.5f);
                float fg = fmaf(tf_, 0.5f, 0.5f);
                float og = fmaf(to, 0.5f, 0.5f);
                creg  = fg * creg + ig * tg;
                TANHA(tc, creg);
                hlast = og * tc;

                if (!last) {
                    unsigned doff = (unsigned)((g * 2 + nb) * SHG_ULL * 8) + hoff;
                    unsigned moff = (unsigned)(MBAR_OFF
                                    + (((nb * NGR + g) * CL + slice) * 8));
                    ull hv = dupf(hlast);
                    #pragma unroll
                    for (int r = 0; r < CL; r++)
                        st_async8(pbase[r] + doff, hv, pbase[r] + moff);
                }
            } else {
                BAR_ARRIVE(g + 1);     // producers: non-blocking, flow on
            }
        }
    }

    // ---- outputs: rnn_outputs @0, logits @65536, h @67584, c @133120 ----
    {
        size_t idx = (size_t)(b0c + eb) * HH + slice * 32 + jl;
        out[idx]          = hlast;
        out[67584 + idx]  = hlast;
        out[133120 + idx] = creg;
    }
    CLUSTER_SYNC();            // no CTA exits while peers may still target our smem
}

// ---------------- output projection ----------------
__global__ void logits_kernel(const float* __restrict__ hbase,
                              const float* __restrict__ W_out,
                              const float* __restrict__ b_out,
                              float* __restrict__ out_logits) {
    int b = blockIdx.x;
    int d = threadIdx.x >> 5;
    int lane = threadIdx.x & 31;
    const float* hr = hbase + (size_t)b * HH;
    const float* wr = W_out + (size_t)d * HH;
    float s = 0.f;
    #pragma unroll
    for (int k = lane; k < HH; k += 32) s += hr[k] * wr[k];
    #pragma unroll
    for (int o = 16; o; o >>= 1) s += __shfl_down_sync(0xffffffffu, s, o);
    if (lane == 0) out_logits[b * DOUT + d] = s + b_out[d];
}

// ---------------- launch ----------------
extern "C" void kernel_launch(void* const* d_in, const int* in_sizes, int n_in,
                              void* d_out, int out_size) {
    const float* x     = (const float*)d_in[0];
    const float* h0    = (const float*)d_in[1];
    const float* c0    = (const float*)d_in[2];
    const float* W_ih  = (const float*)d_in[3];
    const float* W_hh  = (const float*)d_in[4];
    const float* bias  = (const float*)d_in[5];
    const float* W_out = (const float*)d_in[6];
    const float* b_out = (const float*)d_in[7];
    float* out = (float*)d_out;

    static int cfg_done = 0;
    if (!cfg_done) {
        cudaFuncSetAttribute(lstm_kernel, cudaFuncAttributeMaxDynamicSharedMemorySize,
                             LSTM_SMEM);
        cudaFuncSetAttribute(xproj_kernel, cudaFuncAttributeMaxDynamicSharedMemorySize,
                             XP_SMEM);
        cfg_done = 1;
    }

    reorder_whh_kernel<<<HH, 256>>>(W_hh);
    reorder_wih_kernel<<<GG, 64>>>(W_ih, bias);

    xproj_kernel<<<dim3((BB_ * TT) / 64, GG / 128), 256, XP_SMEM>>>(x);

    lstm_kernel<<<NCTA, NT, LSTM_SMEM>>>(h0, c0, out);

    logits_kernel<<<BB_, 256>>>(out, W_out, b_out, out + 65536);
}

// round 16
// speedup vs baseline: 1.0444x; 1.0426x over previous
#include <cuda_runtime.h>
#include <cstdint>

typedef unsigned long long ull;

#define TT 512
#define BB_ 256
#define DIN 64
#define HH 256
#define GG 1024   // 4*H
#define DOUT 8

#define CL 8            // CTAs per cluster
#define NCLUST 16       // clusters
#define NBC 16          // batches per cluster
#define NGR 4           // pipeline groups
#define NBGR 4          // batches per group
#define NCTA (NCLUST*CL)
#define NTC 512         // compute threads (16 warps)
#define NT  640         // + 4 epilogue warps
#define BAR_CNT (NTC + 32)   // 544 per group barrier

// ---------------- device scratch (static, allowed) ----------------
__device__ __align__(128) float g_Xp[(size_t)BB_*TT*GG];   // [b][t][rr]
__device__ __align__(128) float g_Wt[(size_t)HH*GG];       // [k][rr] reordered W_hh
__device__ __align__(128) float g_Wr_ih[(size_t)GG*DIN];
__device__ __align__(128) float g_br[GG];

// ---------------- helpers ----------------
__device__ __forceinline__ ull dupf(float f){ unsigned u=__float_as_uint(f); return (ull)u | ((ull)u<<32); }
__device__ __forceinline__ float lof(ull v){ return __uint_as_float((unsigned)v); }
__device__ __forceinline__ float hif(ull v){ return __uint_as_float((unsigned)(v>>32)); }
#define FMA2(acc,a,b) asm("fma.rn.f32x2 %0, %1, %2, %0;" : "+l"(acc) : "l"(a), "l"(b))
#define ADD2(d,a,b)   asm("add.rn.f32x2 %0, %1, %2;" : "=l"(d) : "l"(a), "l"(b))
#define TANHA(d,x)    asm("tanh.approx.f32 %0, %1;" : "=f"(d) : "f"(x))

#define CLUSTER_SYNC() do { \
    asm volatile("barrier.cluster.arrive.aligned;" ::: "memory"); \
    asm volatile("barrier.cluster.wait.aligned;"   ::: "memory"); } while(0)

// producer/consumer named barriers (ids 1..4)
#define BAR_ARRIVE(id) asm volatile("bar.arrive %0, %1;" :: "r"(id), "r"(BAR_CNT) : "memory")
#define BAR_SYNCN(id)  asm volatile("bar.sync %0, %1;"   :: "r"(id), "r"(BAR_CNT) : "memory")

__device__ __forceinline__ void mbar_init(unsigned a, unsigned cnt){
    asm volatile("mbarrier.init.shared.b64 [%0], %1;" :: "r"(a), "r"(cnt) : "memory");
}
__device__ __forceinline__ void mbar_expect(unsigned a, unsigned tx){
    asm volatile("mbarrier.arrive.expect_tx.shared.b64 _, [%0], %1;" :: "r"(a), "r"(tx) : "memory");
}
__device__ __forceinline__ void mbar_wait_par(unsigned a, unsigned ph){
    asm volatile(
        "{\n\t.reg .pred P;\n"
        "W1_%=:\n\t"
        "mbarrier.try_wait.parity.acquire.cta.shared::cta.b64 P, [%0], %1, 0x989680;\n\t"
        "@P bra W2_%=;\n\t"
        "bra W1_%=;\n"
        "W2_%=:\n\t}"
        :: "r"(a), "r"(ph) : "memory");
}
__device__ __forceinline__ unsigned mapa_sh(unsigned addr, unsigned rank){
    unsigned r;
    asm("mapa.shared::cluster.u32 %0, %1, %2;" : "=r"(r) : "r"(addr), "r"(rank));
    return r;
}
__device__ __forceinline__ void st_async8(unsigned raddr, ull v, unsigned rmbar){
    asm volatile("st.async.weak.shared::cluster.mbarrier::complete_tx::bytes.b64 [%0], %1, [%2];"
                 :: "r"(raddr), "l"(v), "r"(rmbar) : "memory");
}

// ---------------- weight reorder (one-time) ----------------
// rr = 4*j + g  (g in order i,f,g,o), orig row = g*H + j
__global__ void reorder_whh_kernel(const float* __restrict__ W_hh) {
    int k = blockIdx.x;
    for (int rr = threadIdx.x; rr < GG; rr += blockDim.x) {
        int jj = rr >> 2, g = rr & 3;
        g_Wt[(size_t)k * GG + rr] = W_hh[(size_t)(g * HH + jj) * HH + k];
    }
}

__global__ void reorder_wih_kernel(const float* __restrict__ W_ih,
                                   const float* __restrict__ bias) {
    int rr = blockIdx.x;
    int jj = rr >> 2, g = rr & 3;
    int orig = g * HH + jj;
    if (threadIdx.x < DIN)
        g_Wr_ih[(size_t)rr * DIN + threadIdx.x] = W_ih[(size_t)orig * DIN + threadIdx.x];
    if (threadIdx.x == 0) g_br[rr] = bias[orig];
}

// ---------------- input projection GEMM (f32x2, 64m x 128n tile) ----------------
#define XP_SMEM (DIN*66*8 + DIN*132*4)   // As2 + Bs = 67584
__global__ void __launch_bounds__(256) xproj_kernel(const float* __restrict__ x) {
    extern __shared__ __align__(16) char xsm[];
    ull*   As2 = (ull*)xsm;                 // [k][66] dup'd x
    float* Bs  = (float*)(As2 + DIN * 66);  // [k][132]
    int m0 = blockIdx.x * 64, n0 = blockIdx.y * 128;
    int tid = threadIdx.x;

    for (int i = tid; i < 1024; i += 256) {
        int r  = i >> 4;       // m row 0..63
        int kq = i & 15;
        float4 v = ((const float4*)(x + (size_t)(m0 + r) * DIN))[kq];
        As2[(kq*4+0)*66 + r] = dupf(v.x); As2[(kq*4+1)*66 + r] = dupf(v.y);
        As2[(kq*4+2)*66 + r] = dupf(v.z); As2[(kq*4+3)*66 + r] = dupf(v.w);
    }
    for (int i = tid; i < 2048; i += 256) {
        int r  = i >> 4;       // n row 0..127
        int kq = i & 15;
        float4 w = ((const float4*)(g_Wr_ih + (size_t)(n0 + r) * DIN))[kq];
        Bs[(kq*4+0)*132 + r] = w.x; Bs[(kq*4+1)*132 + r] = w.y;
        Bs[(kq*4+2)*132 + r] = w.z; Bs[(kq*4+3)*132 + r] = w.w;
    }
    __syncthreads();

    int tm = (tid >> 4) << 2;     // 4 m rows
    int tn = (tid & 15) << 3;     // 8 n cols (4 f32x2 pairs)
    ull acc[4][4] = {};
    #pragma unroll 8
    for (int k = 0; k < DIN; k++) {
        ulonglong2 a01 = *(const ulonglong2*)&As2[k*66 + tm];
        ulonglong2 a23 = *(const ulonglong2*)&As2[k*66 + tm + 2];
        ulonglong2 b01 = *(const ulonglong2*)&Bs[k*132 + tn];
        ulonglong2 b23 = *(const ulonglong2*)&Bs[k*132 + tn + 4];
        ull am[4] = {a01.x, a01.y, a23.x, a23.y};
        #pragma unroll
        for (int i = 0; i < 4; i++) {
            FMA2(acc[i][0], am[i], b01.x); FMA2(acc[i][1], am[i], b01.y);
            FMA2(acc[i][2], am[i], b23.x); FMA2(acc[i][3], am[i], b23.y);
        }
    }
    ulonglong2 bias01 = *(const ulonglong2*)(g_br + n0 + tn);
    ulonglong2 bias23 = *(const ulonglong2*)(g_br + n0 + tn + 4);
    #pragma unroll
    for (int i = 0; i < 4; i++) {
        ulonglong2 r0, r1;
        ADD2(r0.x, acc[i][0], bias01.x); ADD2(r0.y, acc[i][1], bias01.y);
        ADD2(r1.x, acc[i][2], bias23.x); ADD2(r1.y, acc[i][3], bias23.y);
        float* orow = g_Xp + (size_t)(m0 + tm + i) * GG + n0 + tn;
        *(ulonglong2*)orow       = r0;
        *(ulonglong2*)(orow + 4) = r1;
    }
}

// ---------------- LSTM recurrence: per-group epilogue warps ----------------
// smem: shG [4 g][2 par][4 b][256 k] ull 64KB | red [4 g][4b][16kq][64p] ull 128KB | mbar[8]
#define SHG_ULL    (NBGR*HH)                // 1024 per (group,parity)
#define REDB_ULL   (NBGR*16*64)             // 4096 per group buffer
#define RED_OFF_B  (NGR*2*SHG_ULL*8)        // 65536
#define MBAR_OFF   (RED_OFF_B + NGR*REDB_ULL*8)  // 65536+131072=196608
#define LSTM_SMEM  (MBAR_OFF + 128)

__global__ void __launch_bounds__(NT, 1) __cluster_dims__(CL, 1, 1)
lstm_kernel(const float* __restrict__ h0, const float* __restrict__ c0,
            float* __restrict__ out) {
    extern __shared__ __align__(16) char smem[];
    ull*   shg  = (ull*)smem;                        // [(g*2+par)*1024 + b*256 + k]
    ull*   redb = (ull*)(smem + RED_OFF_B);          // [g][b][kq][pair]
    const unsigned sh_u32 = (unsigned)__cvta_generic_to_shared(smem);

    const int tid   = threadIdx.x;
    const int wid   = tid >> 5;
    const int lane  = tid & 31;
    const int slice = blockIdx.x & (CL - 1);
    const int cl    = blockIdx.x >> 3;
    const int b0c   = cl * NBC;

    // ---- common prologue ----
    if (tid < 8) mbar_init(sh_u32 + MBAR_OFF + tid * 8, 1);

    // init parity-0 buffers from h0 (all threads)
    for (int i = tid; i < NBC * HH; i += NT) {
        int b = i >> 8, k = i & 255;
        shg[((b >> 2) * 2) * SHG_ULL + (b & 3) * HH + k] =
            dupf(h0[(size_t)(b0c + b) * HH + k]);
    }
    __syncthreads();
    CLUSTER_SYNC();            // mbarriers initialized cluster-wide before any st.async

    if (wid < 16) {
        // ================= COMPUTE WARPS (pure) =================
        const int kq    = wid;                 // 0..15, 16 k each
        const int pg    = lane;
        const int kbase = kq * 16;

        ull wreg[32];
        #pragma unroll
        for (int kk = 0; kk < 16; kk++) {
            ulonglong2 w2 = *(const ulonglong2*)(g_Wt + (size_t)(kbase + kk) * GG
                                                 + slice * 128 + 4 * pg);
            wreg[2*kk]     = w2.x;
            wreg[2*kk + 1] = w2.y;
        }

        unsigned ph0[NGR] = {0,0,0,0};
        unsigned ph1[NGR] = {0,0,0,0};

        #pragma unroll 1
        for (int t = 0; t < TT; t++) {
            const int par = t & 1, nb = par ^ 1;
            const int last = (t == TT - 1);

            #pragma unroll
            for (int g = 0; g < NGR; g++) {
                const unsigned mb_par = sh_u32 + MBAR_OFF + (unsigned)((g * 2 + par) * 8);
                const unsigned mb_nb  = sh_u32 + MBAR_OFF + (unsigned)((g * 2 + nb) * 8);

                if (t) {
                    if (par) { mbar_wait_par(mb_par, ph1[g]); ph1[g] ^= 1; }
                    else     { mbar_wait_par(mb_par, ph0[g]); ph0[g] ^= 1; }
                }

                const ull* gb = shg + (size_t)(g * 2 + par) * SHG_ULL;
                ull* rb = redb + (size_t)g * REDB_ULL;
                #pragma unroll
                for (int b = 0; b < NBGR; b++) {
                    const ulonglong2* hp = (const ulonglong2*)(gb + b * HH + kbase);
                    ull a0 = 0ull, a1 = 0ull, a2 = 0ull, a3 = 0ull;
                    #pragma unroll
                    for (int kk = 0; kk < 16; kk += 2) {
                        ulonglong2 h2 = hp[kk >> 1];
                        FMA2(a0, wreg[2*kk],     h2.x);
                        FMA2(a1, wreg[2*kk + 1], h2.x);
                        FMA2(a2, wreg[2*kk + 2], h2.y);
                        FMA2(a3, wreg[2*kk + 3], h2.y);
                    }
                    ulonglong2 s;
                    ADD2(s.x, a0, a2);
                    ADD2(s.y, a1, a3);
                    *(ulonglong2*)(rb + (b * 16 + kq) * 64 + 2 * pg) = s;
                }

                if (tid == 0 && !last) mbar_expect(mb_nb, 8192);
                BAR_ARRIVE(g + 1);     // non-blocking; flow into next group
            }
        }
    } else {
        // ================= EPILOGUE WARPS (one per group) =================
        const int g = wid - 16;                // my group
        // lane owns j = slice*32 + lane, batches b = g*4 + q (q=0..3)
        float creg[NBGR], hlast[NBGR];
        float4 xv[NBGR];
        #pragma unroll
        for (int q = 0; q < NBGR; q++) {
            creg[q] = c0[(size_t)(b0c + g * 4 + q) * HH + slice * 32 + lane];
            xv[q] = *(const float4*)(g_Xp + ((size_t)(b0c + g * 4 + q) * TT + 0) * GG
                                     + slice * 128 + 4 * lane);
        }

        unsigned pbase[CL];
        #pragma unroll
        for (int r = 0; r < CL; r++) pbase[r] = mapa_sh(sh_u32, r);

        #pragma unroll 1
        for (int t = 0; t < TT; t++) {
            const int nb = (t & 1) ^ 1;
            const int last = (t == TT - 1);

            BAR_SYNCN(g + 1);          // all compute warps' red[g] writes done

            #pragma unroll
            for (int q = 0; q < NBGR; q++) {
                const ull* rp = redb + (size_t)g * REDB_ULL + (q * 16) * 64 + 2 * lane;
                ull sx[8], sy[8];
                #pragma unroll
                for (int u = 0; u < 8; u++) {
                    ulonglong2 a = *(const ulonglong2*)(rp + (2*u) * 64);
                    ulonglong2 b = *(const ulonglong2*)(rp + (2*u + 1) * 64);
                    ADD2(sx[u], a.x, b.x);
                    ADD2(sy[u], a.y, b.y);
                }
                ull sif, sgo, t0, t1, t2, t3;
                ADD2(t0, sx[0], sx[1]); ADD2(t1, sx[2], sx[3]);
                ADD2(t2, sx[4], sx[5]); ADD2(t3, sx[6], sx[7]);
                ADD2(t0, t0, t1); ADD2(t2, t2, t3); ADD2(sif, t0, t2);
                ADD2(t0, sy[0], sy[1]); ADD2(t1, sy[2], sy[3]);
                ADD2(t2, sy[4], sy[5]); ADD2(t3, sy[6], sy[7]);
                ADD2(t0, t0, t1); ADD2(t2, t2, t3); ADD2(sgo, t0, t2);

                float pi  = xv[q].x + lof(sif);
                float pf  = xv[q].y + hif(sif);
                float pgx = xv[q].z + lof(sgo);
                float po  = xv[q].w + hif(sgo);
                float ti, tf_, tg, to, tc;
                TANHA(ti, pi * 0.5f); TANHA(tf_, pf * 0.5f);
                TANHA(tg, pgx);       TANHA(to, po * 0.5f);
                float ig = fmaf(ti, 0.5f, 0.5f);
                float fg = fmaf(tf_, 0.5f, 0.5f);
                float og = fmaf(to, 0.5f, 0.5f);
                creg[q] = fg * creg[q] + ig * tg;
                TANHA(tc, creg[q]);
                hlast[q] = og * tc;

                if (!last) {
                    unsigned doff = (unsigned)((g * 2 + nb) * SHG_ULL * 8)
                                    + (unsigned)((q * HH + slice * 32 + lane) * 8);
                    unsigned moff = (unsigned)(MBAR_OFF + (g * 2 + nb) * 8);
                    ull hv = dupf(hlast[q]);
                    #pragma unroll
                    for (int r = 0; r < CL; r++)
                        st_async8(pbase[r] + doff, hv, pbase[r] + moff);
                }
            }

            // prefetch x(t+1) into registers — a full step of latency cover
            if (!last) {
                #pragma unroll
                for (int q = 0; q < NBGR; q++)
                    xv[q] = *(const float4*)(g_Xp
                              + ((size_t)(b0c + g * 4 + q) * TT + (t + 1)) * GG
                              + slice * 128 + 4 * lane);
            }
        }

        // ---- outputs: rnn_outputs @0, logits @65536, h @67584, c @133120 ----
        #pragma unroll
        for (int q = 0; q < NBGR; q++) {
            size_t idx = (size_t)(b0c + g * 4 + q) * HH + slice * 32 + lane;
            out[idx]          = hlast[q];
            out[67584 + idx]  = hlast[q];
            out[133120 + idx] = creg[q];
        }
    }

    CLUSTER_SYNC();            // no CTA exits while peers may still target our smem
}

// ---------------- output projection ----------------
__global__ void logits_kernel(const float* __restrict__ hbase,
                              const float* __restrict__ W_out,
                              const float* __restrict__ b_out,
                              float* __restrict__ out_logits) {
    int b = blockIdx.x;
    int d = threadIdx.x >> 5;
    int lane = threadIdx.x & 31;
    const float* hr = hbase + (size_t)b * HH;
    const float* wr = W_out + (size_t)d * HH;
    float s = 0.f;
    #pragma unroll
    for (int k = lane; k < HH; k += 32) s += hr[k] * wr[k];
    #pragma unroll
    for (int o = 16; o; o >>= 1) s += __shfl_down_sync(0xffffffffu, s, o);
    if (lane == 0) out_logits[b * DOUT + d] = s + b_out[d];
}

// ---------------- launch ----------------
extern "C" void kernel_launch(void* const* d_in, const int* in_sizes, int n_in,
                              void* d_out, int out_size) {
    const float* x     = (const float*)d_in[0];
    const float* h0    = (const float*)d_in[1];
    const float* c0    = (const float*)d_in[2];
    const float* W_ih  = (const float*)d_in[3];
    const float* W_hh  = (const float*)d_in[4];
    const float* bias  = (const float*)d_in[5];
    const float* W_out = (const float*)d_in[6];
    const float* b_out = (const float*)d_in[7];
    float* out = (float*)d_out;

    static int cfg_done = 0;
    if (!cfg_done) {
        cudaFuncSetAttribute(lstm_kernel, cudaFuncAttributeMaxDynamicSharedMemorySize,
                             LSTM_SMEM);
        cudaFuncSetAttribute(xproj_kernel, cudaFuncAttributeMaxDynamicSharedMemorySize,
                             XP_SMEM);
        cfg_done = 1;
    }

    reorder_whh_kernel<<<HH, 256>>>(W_hh);
    reorder_wih_kernel<<<GG, 64>>>(W_ih, bias);

    xproj_kernel<<<dim3((BB_ * TT) / 64, GG / 128), 256, XP_SMEM>>>(x);

    lstm_kernel<<<NCTA, NT, LSTM_SMEM>>>(h0, c0, out);

    logits_kernel<<<BB_, 256>>>(out, W_out, b_out, out + 65536);
}